// round 1
// baseline (speedup 1.0000x reference)
#include <cuda_runtime.h>

// Problem constants (from reference)
#define S 2048
#define C 4096
#define K 4

// Each thread computes 4 consecutive channels of one sample via float4 store.
// grid: (C / (256*4), S) = (4, 2048); block: 256 threads.
__global__ void __launch_bounds__(256, 8)
smf_kernel(const float* __restrict__ comp,      // (K, C)
           const float* __restrict__ contrib,   // (S, K)
           const float* __restrict__ shift,     // (S, K)
           float* __restrict__ out)             // (S, C)
{
    const int s  = blockIdx.y;
    const int c0 = (blockIdx.x * blockDim.x + threadIdx.x) * 4;

    float acc0 = 0.f, acc1 = 0.f, acc2 = 0.f, acc3 = 0.f;

#pragma unroll
    for (int k = 0; k < K; k++) {
        const float sh = __ldg(&shift[s * K + k]);
        const float w  = __ldg(&contrib[s * K + k]);
        const float m  = floorf(sh);
        const float f  = sh - m;
        const int   mi = (int)m;
        const float* ck = comp + k * C;

        const int base = c0 + mi;   // index of tap0 for channel c0

        // Load 5 consecutive component values (tap0..tap0+4), bounds-checked.
        float v[5];
#pragma unroll
        for (int j = 0; j < 5; j++) {
            const int idx = base + j;
            v[j] = (idx >= 0 && idx < C) ? __ldg(&ck[idx]) : 0.f;
        }

        const float w0 = w * (1.f - f);
        const float w1 = w * f;
        acc0 = fmaf(w0, v[0], fmaf(w1, v[1], acc0));
        acc1 = fmaf(w0, v[1], fmaf(w1, v[2], acc1));
        acc2 = fmaf(w0, v[2], fmaf(w1, v[3], acc2));
        acc3 = fmaf(w0, v[3], fmaf(w1, v[4], acc3));
    }

    float4 o = make_float4(acc0, acc1, acc2, acc3);
    *reinterpret_cast<float4*>(out + (size_t)s * C + c0) = o;
}

extern "C" void kernel_launch(void* const* d_in, const int* in_sizes, int n_in,
                              void* d_out, int out_size) {
    // metadata order: inputs (unused), components, contributions, shift
    const float* comp    = (const float*)d_in[1];
    const float* contrib = (const float*)d_in[2];
    const float* shift   = (const float*)d_in[3];
    float*       out     = (float*)d_out;

    dim3 grid(C / (256 * 4), S);
    dim3 block(256);
    smf_kernel<<<grid, block>>>(comp, contrib, shift, out);
}

// round 2
// speedup vs baseline: 1.2892x; 1.2892x over previous
#include <cuda_runtime.h>

#define S 2048
#define C 4096
#define K 4

// Compile-time tap selection: h[R..R+4] out of {own.xyzw, nxt.xyzw}.
// All indexing is compile-time -> pure register wiring, no FSEL chain.
template<int R>
__device__ __forceinline__ void tap_fma(float4 own, float4 nxt, float w0, float w1,
                                        float& a0, float& a1, float& a2, float& a3) {
    const float h[8] = {own.x, own.y, own.z, own.w, nxt.x, nxt.y, nxt.z, nxt.w};
    a0 = fmaf(w0, h[R + 0], fmaf(w1, h[R + 1], a0));
    a1 = fmaf(w0, h[R + 1], fmaf(w1, h[R + 2], a1));
    a2 = fmaf(w0, h[R + 2], fmaf(w1, h[R + 3], a2));
    a3 = fmaf(w0, h[R + 3], fmaf(w1, h[R + 4], a3));
}

// Each warp handles 128 consecutive channels of one sample.
// Lane t computes channels c0w + 4t .. c0w + 4t + 3 and stores one float4.
// grid: (C/1024, S) = (4, 2048); block: 256 threads (8 warps).
__global__ void __launch_bounds__(256, 8)
smf_kernel(const float* __restrict__ comp,      // (K, C)
           const float* __restrict__ contrib,   // (S, K)
           const float* __restrict__ shift,     // (S, K)
           float* __restrict__ out)             // (S, C)
{
    const int s    = blockIdx.y;
    const int warp = threadIdx.x >> 5;
    const int lane = threadIdx.x & 31;
    const int c0w  = blockIdx.x * 1024 + warp * 128;   // warp's first channel

    float a0 = 0.f, a1 = 0.f, a2 = 0.f, a3 = 0.f;

#pragma unroll
    for (int k = 0; k < K; k++) {
        const float sh = __ldg(&shift[s * K + k]);
        const float w  = __ldg(&contrib[s * K + k]);
        const float m  = floorf(sh);
        const float f  = sh - m;
        const float w0 = w * (1.f - f);
        const float w1 = w * f;
        const int   mi = (int)m;

        const int a     = c0w + mi;       // global index of lane0's first tap
        const int base4 = a >> 2;         // arithmetic shift: floors negatives
        const int r     = a & 3;

        // Fast path: the 33 float4 window [base4, base4+32] lies inside comp row.
        if (base4 >= 0 && base4 <= (C / 4 - 33)) {
            const float4* c4 = reinterpret_cast<const float4*>(comp + k * C);
            float4 own = __ldg(&c4[base4 + lane]);   // coalesced, aligned
            float4 ext = __ldg(&c4[base4 + 32]);     // broadcast (1 wavefront)

            float4 nxt;
            nxt.x = __shfl_down_sync(0xffffffffu, own.x, 1);
            nxt.y = __shfl_down_sync(0xffffffffu, own.y, 1);
            nxt.z = __shfl_down_sync(0xffffffffu, own.z, 1);
            nxt.w = __shfl_down_sync(0xffffffffu, own.w, 1);
            if (lane == 31) nxt = ext;               // lane31's neighbor window

            switch (r) {                              // warp-uniform branch
                case 0:  tap_fma<0>(own, nxt, w0, w1, a0, a1, a2, a3); break;
                case 1:  tap_fma<1>(own, nxt, w0, w1, a0, a1, a2, a3); break;
                case 2:  tap_fma<2>(own, nxt, w0, w1, a0, a1, a2, a3); break;
                default: tap_fma<3>(own, nxt, w0, w1, a0, a1, a2, a3); break;
            }
        } else {
            // Slow path (edge warps only): scalar, bounds-checked.
            const float* ck = comp + k * C;
            const int b = a + 4 * lane;
            float v[5];
#pragma unroll
            for (int j = 0; j < 5; j++) {
                const int idx = b + j;
                v[j] = (idx >= 0 && idx < C) ? __ldg(&ck[idx]) : 0.f;
            }
            a0 = fmaf(w0, v[0], fmaf(w1, v[1], a0));
            a1 = fmaf(w0, v[1], fmaf(w1, v[2], a1));
            a2 = fmaf(w0, v[2], fmaf(w1, v[3], a2));
            a3 = fmaf(w0, v[3], fmaf(w1, v[4], a3));
        }
    }

    const int c = c0w + 4 * lane;
    *reinterpret_cast<float4*>(out + (size_t)s * C + c) = make_float4(a0, a1, a2, a3);
}

extern "C" void kernel_launch(void* const* d_in, const int* in_sizes, int n_in,
                              void* d_out, int out_size) {
    // metadata order: inputs (unused), components, contributions, shift
    const float* comp    = (const float*)d_in[1];
    const float* contrib = (const float*)d_in[2];
    const float* shift   = (const float*)d_in[3];
    float*       out     = (float*)d_out;

    dim3 grid(C / 1024, S);
    dim3 block(256);
    smf_kernel<<<grid, block>>>(comp, contrib, shift, out);
}